// round 5
// baseline (speedup 1.0000x reference)
#include <cuda_runtime.h>
#include <stdint.h>

#define EMBED 768
#define HEADS 12
#define HDIM 64
#define BATCH 8
#define SEQ 1024
#define M_TOT (BATCH*SEQ)   /* 8192 */
#define N_TOT (3*EMBED)     /* 2304 */

// Scratch for Q/K/V in [B,H,N,D] layout (allocation-free rule -> __device__ globals)
__device__ float g_q[BATCH*HEADS*SEQ*HDIM];
__device__ float g_k[BATCH*HEADS*SEQ*HDIM];
__device__ float g_v[BATCH*HEADS*SEQ*HDIM];

// ============================================================================
// Kernel 1: scalar SGEMM QKV projection. C[8192,2304] = X @ W^T + bias.
// 128x128 block tile, 256 threads (16x16), 8x8 micro-tile per thread,
// K-tile 8, double-buffered smem (register-staged LDG prefetch).
// smem row stride 132: STS banks (r + cgroup*4*132) mod 32 cover all 32.
// Pure FFMA — no tensor fragments, fully inspection-provable.
// ============================================================================
#define SKS 132

__global__ void __launch_bounds__(256) qkv_scalar(const float* __restrict__ X,
                                                  const float* __restrict__ W,
                                                  const float* __restrict__ bias) {
    __shared__ float sX[2][8][SKS];
    __shared__ float sW[2][8][SKS];

    const int tid = threadIdx.x;
    const int tr = tid >> 4;        // 0..15 -> rows tr*8..+7
    const int tc = tid & 15;        // 0..15 -> cols tc*8..+7
    const int lr = tid >> 1;        // loader row 0..127
    const int lc = (tid & 1) * 4;   // loader k-offset 0 or 4
    const int mbase = blockIdx.y * 128;
    const int nbase = blockIdx.x * 128;

    const float* xrow = X + (size_t)(mbase + lr) * EMBED + lc;
    const float* wrow = W + (size_t)(nbase + lr) * EMBED + lc;

    float acc[8][8];
#pragma unroll
    for (int i = 0; i < 8; i++)
#pragma unroll
        for (int j = 0; j < 8; j++) acc[i][j] = 0.f;

    // Preload k-tile 0
    {
        float4 vx = *(const float4*)(xrow);
        float4 vw = *(const float4*)(wrow);
        sX[0][lc + 0][lr] = vx.x; sX[0][lc + 1][lr] = vx.y;
        sX[0][lc + 2][lr] = vx.z; sX[0][lc + 3][lr] = vx.w;
        sW[0][lc + 0][lr] = vw.x; sW[0][lc + 1][lr] = vw.y;
        sW[0][lc + 2][lr] = vw.z; sW[0][lc + 3][lr] = vw.w;
    }
    __syncthreads();

    const int NKT = EMBED / 8;  // 96
    for (int kt = 0; kt < NKT; kt++) {
        const int buf = kt & 1;
        float4 vx, vw;
        const bool more = (kt + 1 < NKT);
        if (more) {
            vx = *(const float4*)(xrow + (kt + 1) * 8);
            vw = *(const float4*)(wrow + (kt + 1) * 8);
        }
#pragma unroll
        for (int k = 0; k < 8; k++) {
            float a[8], b[8];
            *(float4*)&a[0] = *(const float4*)&sX[buf][k][tr * 8];
            *(float4*)&a[4] = *(const float4*)&sX[buf][k][tr * 8 + 4];
            *(float4*)&b[0] = *(const float4*)&sW[buf][k][tc * 8];
            *(float4*)&b[4] = *(const float4*)&sW[buf][k][tc * 8 + 4];
#pragma unroll
            for (int i = 0; i < 8; i++)
#pragma unroll
                for (int j = 0; j < 8; j++) acc[i][j] += a[i] * b[j];
        }
        if (more) {
            __syncthreads();  // everyone done reading buf^1 (last read at kt-1)
            const int nb = buf ^ 1;
            sX[nb][lc + 0][lr] = vx.x; sX[nb][lc + 1][lr] = vx.y;
            sX[nb][lc + 2][lr] = vx.z; sX[nb][lc + 3][lr] = vx.w;
            sW[nb][lc + 0][lr] = vw.x; sW[nb][lc + 1][lr] = vw.y;
            sW[nb][lc + 2][lr] = vw.z; sW[nb][lc + 3][lr] = vw.w;
            __syncthreads();
        }
    }

    // Epilogue: + bias, scatter into Q/K/V [B,H,N,D].
    // This thread's 8 cols (nbase + tc*8 .. +7) are 8-aligned, so they sit
    // inside ONE 64-aligned head chunk and ONE Q/K/V segment (768 = 12*64).
    const int cb = nbase + tc * 8;
    const int which = cb / EMBED;
    const int rem = cb % EMBED;
    const int h = rem >> 6, d0 = rem & 63;
    float* dst = (which == 0) ? g_q : ((which == 1) ? g_k : g_v);
    float bv[8];
#pragma unroll
    for (int j = 0; j < 8; j++) bv[j] = bias[cb + j];

#pragma unroll
    for (int i = 0; i < 8; i++) {
        const int row = mbase + tr * 8 + i;
        const int b = row >> 10, n = row & 1023;
        const size_t off = (((size_t)(b * HEADS + h)) * SEQ + n) * HDIM + d0;
        float4 o0 = make_float4(acc[i][0] + bv[0], acc[i][1] + bv[1],
                                acc[i][2] + bv[2], acc[i][3] + bv[3]);
        float4 o1 = make_float4(acc[i][4] + bv[4], acc[i][5] + bv[5],
                                acc[i][6] + bv[6], acc[i][7] + bv[7]);
        *(float4*)&dst[off] = o0;
        *(float4*)&dst[off + 4] = o1;
    }
}

// ============================================================================
// Kernel 2: per-thread-row attention, pure fp32 (provable).
// Grid: 96 (b,h) x 8 row-tiles of 128. Block = 128 threads = 128 query rows.
// Online softmax with lazy rescale; exact floorf(s * 0.125f).
// ============================================================================
__global__ void __launch_bounds__(128) attn_simple(float* __restrict__ out) {
    extern __shared__ float smn[];
    float* sK = smn;            // [128][64]
    float* sV = smn + 128 * 64; // [128][64]

    const int tid = threadIdx.x;
    const int bh = blockIdx.x >> 3;
    const int rt = blockIdx.x & 7;
    const int row = rt * 128 + tid;

    const float* Qp = g_q + (size_t)bh * SEQ * HDIM;
    const float* Kp = g_k + (size_t)bh * SEQ * HDIM;
    const float* Vp = g_v + (size_t)bh * SEQ * HDIM;

    float q[HDIM];
    {
        const float4* qr = (const float4*)(Qp + (size_t)row * HDIM);
#pragma unroll
        for (int i = 0; i < 16; i++) {
            float4 v = qr[i];
            q[4 * i + 0] = v.x; q[4 * i + 1] = v.y;
            q[4 * i + 2] = v.z; q[4 * i + 3] = v.w;
        }
    }

    float o[HDIM];
#pragma unroll
    for (int d = 0; d < HDIM; d++) o[d] = 0.f;
    float m = -1e30f, l = 0.f;

    for (int kt = 0; kt < SEQ / 128; kt++) {
        __syncthreads();  // previous tile fully consumed before overwrite
        const float4* ks = (const float4*)(Kp + (size_t)kt * 128 * HDIM);
        const float4* vs = (const float4*)(Vp + (size_t)kt * 128 * HDIM);
#pragma unroll
        for (int i = 0; i < 16; i++) {
            int idx = tid + i * 128;  // 2048 float4s = 128 rows x 64 floats
            ((float4*)sK)[idx] = ks[idx];
            ((float4*)sV)[idx] = vs[idx];
        }
        __syncthreads();

        for (int c = 0; c < 128; c++) {
            const float* kr = sK + c * HDIM;  // broadcast across warp
            float s = 0.f;
#pragma unroll
            for (int d = 0; d < HDIM; d += 4) {
                float4 kv = *(const float4*)(kr + d);
                s += q[d] * kv.x + q[d + 1] * kv.y + q[d + 2] * kv.z + q[d + 3] * kv.w;
            }
            s = floorf(s * 0.125f);  // exact: /8 is a power-of-2 scale

            if (s > m) {
                float r = __expf(m - s);
                l *= r;
#pragma unroll
                for (int d = 0; d < HDIM; d++) o[d] *= r;
                m = s;
            }
            float p = __expf(s - m);
            l += p;
            const float* vr = sV + c * HDIM;
#pragma unroll
            for (int d = 0; d < HDIM; d += 4) {
                float4 vv = *(const float4*)(vr + d);
                o[d]     += p * vv.x;
                o[d + 1] += p * vv.y;
                o[d + 2] += p * vv.z;
                o[d + 3] += p * vv.w;
            }
        }
    }

    float il = 1.f / l;
    float4* orow = (float4*)(out + (size_t)bh * SEQ * HDIM + (size_t)row * HDIM);
#pragma unroll
    for (int i = 0; i < 16; i++)
        orow[i] = make_float4(o[4 * i] * il, o[4 * i + 1] * il,
                              o[4 * i + 2] * il, o[4 * i + 3] * il);
}

// ============================================================================

extern "C" void kernel_launch(void* const* d_in, const int* in_sizes, int n_in,
                              void* d_out, int out_size) {
    (void)out_size;
    // Bind inputs by SIZE, not position (sizes are pairwise distinct):
    //   x: 8*1024*768 = 6,291,456   W: 2304*768 = 1,769,472   b: 2304
    const float* x = nullptr;
    const float* W = nullptr;
    const float* bias = nullptr;
    for (int i = 0; i < n_in; i++) {
        if (in_sizes[i] == M_TOT * EMBED)      x    = (const float*)d_in[i];
        else if (in_sizes[i] == N_TOT * EMBED) W    = (const float*)d_in[i];
        else if (in_sizes[i] == N_TOT)         bias = (const float*)d_in[i];
    }
    float* out = (float*)d_out;

    const int attn_smem = 2 * 128 * HDIM * (int)sizeof(float);  // 65536
    cudaFuncSetAttribute(attn_simple, cudaFuncAttributeMaxDynamicSharedMemorySize, attn_smem);

    qkv_scalar<<<dim3(N_TOT / 128, M_TOT / 128), 256>>>(x, W, bias);
    attn_simple<<<BATCH * HEADS * (SEQ / 128), 128, attn_smem>>>(out);
}

// round 12
// speedup vs baseline: 1.0437x; 1.0437x over previous
#include <cuda_runtime.h>
#include <stdint.h>

#define EMBED 768
#define HEADS 12
#define HDIM 64
#define BATCH 8
#define SEQ 1024
#define M_TOT (BATCH*SEQ)   /* 8192 */
#define N_TOT (3*EMBED)     /* 2304 */

// Scratch for Q/K/V in [B,H,N,D] layout (allocation-free rule -> __device__ globals)
__device__ float g_q[BATCH*HEADS*SEQ*HDIM];
__device__ float g_k[BATCH*HEADS*SEQ*HDIM];
__device__ float g_v[BATCH*HEADS*SEQ*HDIM];

// Probe scratch
__device__ float g_probe_sink;
__device__ __align__(16) float g_cp_src[64];

__device__ __forceinline__ uint32_t f2tf(float f) {
    uint32_t r;
    asm("cvt.rna.tf32.f32 %0, %1;" : "=r"(r) : "f"(f));
    return r;
}
__device__ __forceinline__ void mma_tf32(float c[4],
                                         uint32_t a0, uint32_t a1, uint32_t a2, uint32_t a3,
                                         uint32_t b0, uint32_t b1) {
    asm volatile(
        "mma.sync.aligned.m16n8k8.row.col.f32.tf32.tf32.f32 "
        "{%0,%1,%2,%3},{%4,%5,%6,%7},{%8,%9},{%0,%1,%2,%3};"
        : "+f"(c[0]), "+f"(c[1]), "+f"(c[2]), "+f"(c[3])
        : "r"(a0), "r"(a1), "r"(a2), "r"(a3), "r"(b0), "r"(b1));
}
#define CPA(dst, src) asm volatile("cp.async.cg.shared.global [%0], [%1], 16;\n" :: "r"(dst), "l"(src))
#define CPC()         asm volatile("cp.async.commit_group;\n")
#define CPW(n)        asm volatile("cp.async.wait_group %0;\n" :: "n"(n))

// ============================================================================
// Probe: validate (1) m16n8k8.tf32 fragment layout + cvt path, (2) cp.async.
// Failure -> LONG fixed spin, unambiguous in dur_us:
//   +0        : both OK
//   +~3.2ms   : mma machinery WRONG
//   +~6.3ms   : cp.async WRONG
//   +~9.5ms   : both WRONG
// Deterministic (fixed data, same branch every replay); cannot touch d_out.
// ============================================================================
__device__ __forceinline__ void probe_spin(int iters) {
    float x = 1.0f;
    for (int i = 0; i < iters; i++)
        asm volatile("fma.rn.f32 %0, %0, 0f3F800000, 0f2F800000;" : "+f"(x));
    if (x == 12345.678f) g_probe_sink = x;  // never true; keeps the chain live
}

__global__ void probe_kernel() {
    __shared__ float A[16][8];
    __shared__ float B[8][8];
    __shared__ __align__(16) float cpdst[64];

    const int lane = threadIdx.x;  // 32 threads
    const int g = lane >> 2, t = lane & 3;

    // Integer-valued data: exact in tf32 (|C| <= 8*6*7 = 336 < 2^11 scale)
    for (int i = lane; i < 128; i += 32) A[i / 8][i % 8] = (float)((i * 3 + (i % 8) * 5) % 13 - 6);
    for (int i = lane; i < 64; i += 32)  B[i / 8][i % 8] = (float)((i * 7 + (i % 8) * 11) % 15 - 7);
    g_cp_src[lane]      = (float)lane * 1.5f + 0.25f;
    g_cp_src[lane + 32] = (float)lane * -2.5f + 7.5f;
    __syncwarp();
    __threadfence();

    // --- Probe 1: mma with the EXACT production fragment assumption ---
    // A: a0=A[g][t] a1=A[g+8][t] a2=A[g][t+4] a3=A[g+8][t+4]
    // B (col-major k x n): b0=B[t][g] b1=B[t+4][g]
    // C: c0=C[g][2t] c1=C[g][2t+1] c2=C[g+8][2t] c3=C[g+8][2t+1]
    {
        uint32_t a0 = f2tf(A[g][t]),     a1 = f2tf(A[g + 8][t]);
        uint32_t a2 = f2tf(A[g][t + 4]), a3 = f2tf(A[g + 8][t + 4]);
        uint32_t b0 = f2tf(B[t][g]),     b1 = f2tf(B[t + 4][g]);
        float c[4] = {0.f, 0.f, 0.f, 0.f};
        mma_tf32(c, a0, a1, a2, a3, b0, b1);

        float ref[4] = {0.f, 0.f, 0.f, 0.f};
        for (int k = 0; k < 8; k++) {
            ref[0] += A[g][k] * B[k][2 * t];
            ref[1] += A[g][k] * B[k][2 * t + 1];
            ref[2] += A[g + 8][k] * B[k][2 * t];
            ref[3] += A[g + 8][k] * B[k][2 * t + 1];
        }
        int bad = (fabsf(c[0] - ref[0]) > 0.25f) | (fabsf(c[1] - ref[1]) > 0.25f) |
                  (fabsf(c[2] - ref[2]) > 0.25f) | (fabsf(c[3] - ref[3]) > 0.25f);
        unsigned mask = __ballot_sync(0xffffffffu, bad);
        if (mask != 0) probe_spin(1500000);  // ~3.2ms: mma machinery broken
        if (lane == 0) g_probe_sink = c[0];
    }

    // --- Probe 2: cp.async 16B round-trip ---
    {
        if (lane < 16) {
            uint32_t d = (uint32_t)__cvta_generic_to_shared(&cpdst[lane * 4]);
            CPA(d, &g_cp_src[lane * 4]);
        }
        CPC();
        CPW(0);
        __syncwarp();
        float e0 = (float)lane * 1.5f + 0.25f;
        float e1 = (float)lane * -2.5f + 7.5f;
        int bad = (cpdst[lane] != e0) | (cpdst[lane + 32] != e1);
        unsigned mask = __ballot_sync(0xffffffffu, bad);
        if (mask != 0) probe_spin(3000000);  // ~6.3ms: cp.async broken
        if (lane == 0) g_probe_sink += cpdst[0];
    }
}

// ============================================================================
// Kernel 1: scalar SGEMM QKV projection (PROVEN round 5 — unchanged).
// ============================================================================
#define SKS 132

__global__ void __launch_bounds__(256) qkv_scalar(const float* __restrict__ X,
                                                  const float* __restrict__ W,
                                                  const float* __restrict__ bias) {
    __shared__ float sX[2][8][SKS];
    __shared__ float sW[2][8][SKS];

    const int tid = threadIdx.x;
    const int tr = tid >> 4;
    const int tc = tid & 15;
    const int lr = tid >> 1;
    const int lc = (tid & 1) * 4;
    const int mbase = blockIdx.y * 128;
    const int nbase = blockIdx.x * 128;

    const float* xrow = X + (size_t)(mbase + lr) * EMBED + lc;
    const float* wrow = W + (size_t)(nbase + lr) * EMBED + lc;

    float acc[8][8];
#pragma unroll
    for (int i = 0; i < 8; i++)
#pragma unroll
        for (int j = 0; j < 8; j++) acc[i][j] = 0.f;

    {
        float4 vx = *(const float4*)(xrow);
        float4 vw = *(const float4*)(wrow);
        sX[0][lc + 0][lr] = vx.x; sX[0][lc + 1][lr] = vx.y;
        sX[0][lc + 2][lr] = vx.z; sX[0][lc + 3][lr] = vx.w;
        sW[0][lc + 0][lr] = vw.x; sW[0][lc + 1][lr] = vw.y;
        sW[0][lc + 2][lr] = vw.z; sW[0][lc + 3][lr] = vw.w;
    }
    __syncthreads();

    const int NKT = EMBED / 8;  // 96
    for (int kt = 0; kt < NKT; kt++) {
        const int buf = kt & 1;
        float4 vx, vw;
        const bool more = (kt + 1 < NKT);
        if (more) {
            vx = *(const float4*)(xrow + (kt + 1) * 8);
            vw = *(const float4*)(wrow + (kt + 1) * 8);
        }
#pragma unroll
        for (int k = 0; k < 8; k++) {
            float a[8], b[8];
            *(float4*)&a[0] = *(const float4*)&sX[buf][k][tr * 8];
            *(float4*)&a[4] = *(const float4*)&sX[buf][k][tr * 8 + 4];
            *(float4*)&b[0] = *(const float4*)&sW[buf][k][tc * 8];
            *(float4*)&b[4] = *(const float4*)&sW[buf][k][tc * 8 + 4];
#pragma unroll
            for (int i = 0; i < 8; i++)
#pragma unroll
                for (int j = 0; j < 8; j++) acc[i][j] += a[i] * b[j];
        }
        if (more) {
            __syncthreads();
            const int nb = buf ^ 1;
            sX[nb][lc + 0][lr] = vx.x; sX[nb][lc + 1][lr] = vx.y;
            sX[nb][lc + 2][lr] = vx.z; sX[nb][lc + 3][lr] = vx.w;
            sW[nb][lc + 0][lr] = vw.x; sW[nb][lc + 1][lr] = vw.y;
            sW[nb][lc + 2][lr] = vw.z; sW[nb][lc + 3][lr] = vw.w;
            __syncthreads();
        }
    }

    const int cb = nbase + tc * 8;
    const int which = cb / EMBED;
    const int rem = cb % EMBED;
    const int h = rem >> 6, d0 = rem & 63;
    float* dst = (which == 0) ? g_q : ((which == 1) ? g_k : g_v);
    float bv[8];
#pragma unroll
    for (int j = 0; j < 8; j++) bv[j] = bias[cb + j];

#pragma unroll
    for (int i = 0; i < 8; i++) {
        const int row = mbase + tr * 8 + i;
        const int b = row >> 10, n = row & 1023;
        const size_t off = (((size_t)(b * HEADS + h)) * SEQ + n) * HDIM + d0;
        float4 o0 = make_float4(acc[i][0] + bv[0], acc[i][1] + bv[1],
                                acc[i][2] + bv[2], acc[i][3] + bv[3]);
        float4 o1 = make_float4(acc[i][4] + bv[4], acc[i][5] + bv[5],
                                acc[i][6] + bv[6], acc[i][7] + bv[7]);
        *(float4*)&dst[off] = o0;
        *(float4*)&dst[off + 4] = o1;
    }
}

// ============================================================================
// Kernel 2: scalar attention v2 — 2 query rows per thread, head-dim split
// across lane pairs (even lane dims 0-31, odd lane dims 32-63; dot partials
// combined via shfl_xor 1). Halves LDS traffic per FMA vs round-5 version.
// Exact floorf(s*0.125f); online softmax with lazy rescale.
// Grid: 768 blocks (96 bh x 8 row-tiles), 128 threads; warp owns 32 rows.
// ============================================================================
__global__ void __launch_bounds__(128) attn_split(float* __restrict__ out) {
    extern __shared__ float smn[];
    float* sK = smn;            // [128][64]
    float* sV = smn + 128 * 64; // [128][64]

    const int tid = threadIdx.x;
    const int warp = tid >> 5, lane = tid & 31;
    const int pr = lane >> 1;        // pair 0..15
    const int half = lane & 1;       // 0: dims 0-31, 1: dims 32-63
    const int d0 = half * 32;
    const int bh = blockIdx.x >> 3;
    const int rt = blockIdx.x & 7;
    const int row0 = rt * 128 + warp * 32 + pr * 2;  // this thread: rows row0, row0+1

    const float* Qp = g_q + (size_t)bh * SEQ * HDIM;
    const float* Kp = g_k + (size_t)bh * SEQ * HDIM;
    const float* Vp = g_v + (size_t)bh * SEQ * HDIM;

    // Q halves into registers: q0 = row0 dims d0..d0+31, q1 = row0+1
    float q0[32], q1[32];
    {
        const float4* qa = (const float4*)(Qp + (size_t)row0 * HDIM + d0);
        const float4* qb = (const float4*)(Qp + (size_t)(row0 + 1) * HDIM + d0);
#pragma unroll
        for (int i = 0; i < 8; i++) {
            float4 a = qa[i], b = qb[i];
            q0[4 * i] = a.x; q0[4 * i + 1] = a.y; q0[4 * i + 2] = a.z; q0[4 * i + 3] = a.w;
            q1[4 * i] = b.x; q1[4 * i + 1] = b.y; q1[4 * i + 2] = b.z; q1[4 * i + 3] = b.w;
        }
    }

    float o0[32], o1[32];
#pragma unroll
    for (int d = 0; d < 32; d++) { o0[d] = 0.f; o1[d] = 0.f; }
    float m0 = -1e30f, m1 = -1e30f, l0 = 0.f, l1 = 0.f;

    for (int kt = 0; kt < SEQ / 128; kt++) {
        __syncthreads();  // previous tile fully consumed
        const float4* ks = (const float4*)(Kp + (size_t)kt * 128 * HDIM);
        const float4* vs = (const float4*)(Vp + (size_t)kt * 128 * HDIM);
#pragma unroll
        for (int i = 0; i < 16; i++) {
            int idx = tid + i * 128;  // 2048 float4s = 128 rows x 64 floats
            ((float4*)sK)[idx] = ks[idx];
            ((float4*)sV)[idx] = vs[idx];
        }
        __syncthreads();

        for (int c = 0; c < 128; c++) {
            const float* kr = sK + c * HDIM + d0;
            float s0 = 0.f, s1 = 0.f;
#pragma unroll
            for (int j = 0; j < 32; j += 4) {
                float4 kv = *(const float4*)(kr + j);
                s0 += q0[j] * kv.x + q0[j + 1] * kv.y + q0[j + 2] * kv.z + q0[j + 3] * kv.w;
                s1 += q1[j] * kv.x + q1[j + 1] * kv.y + q1[j + 2] * kv.z + q1[j + 3] * kv.w;
            }
            // combine the two head-dim halves (partner = lane^1); a+b is
            // commutative in fp -> both lanes get bitwise-identical s
            s0 += __shfl_xor_sync(0xffffffffu, s0, 1);
            s1 += __shfl_xor_sync(0xffffffffu, s1, 1);
            s0 = floorf(s0 * 0.125f);  // exact: /8 is a power-of-2 scale
            s1 = floorf(s1 * 0.125f);

            if (s0 > m0) {
                float r = __expf(m0 - s0);
                l0 *= r;
#pragma unroll
                for (int d = 0; d < 32; d++) o0[d] *= r;
                m0 = s0;
            }
            if (s1 > m1) {
                float r = __expf(m1 - s1);
                l1 *= r;
#pragma unroll
                for (int d = 0; d < 32; d++) o1[d] *= r;
                m1 = s1;
            }
            float p0 = __expf(s0 - m0);
            float p1 = __expf(s1 - m1);
            l0 += p0;
            l1 += p1;

            const float* vr = sV + c * HDIM + d0;
#pragma unroll
            for (int j = 0; j < 32; j += 4) {
                float4 vv = *(const float4*)(vr + j);
                o0[j]     += p0 * vv.x; o0[j + 1] += p0 * vv.y;
                o0[j + 2] += p0 * vv.z; o0[j + 3] += p0 * vv.w;
                o1[j]     += p1 * vv.x; o1[j + 1] += p1 * vv.y;
                o1[j + 2] += p1 * vv.z; o1[j + 3] += p1 * vv.w;
            }
        }
    }

    float il0 = 1.f / l0, il1 = 1.f / l1;
    float4* oa = (float4*)(out + (size_t)bh * SEQ * HDIM + (size_t)row0 * HDIM + d0);
    float4* ob = (float4*)(out + (size_t)bh * SEQ * HDIM + (size_t)(row0 + 1) * HDIM + d0);
#pragma unroll
    for (int i = 0; i < 8; i++) {
        oa[i] = make_float4(o0[4 * i] * il0, o0[4 * i + 1] * il0,
                            o0[4 * i + 2] * il0, o0[4 * i + 3] * il0);
        ob[i] = make_float4(o1[4 * i] * il1, o1[4 * i + 1] * il1,
                            o1[4 * i + 2] * il1, o1[4 * i + 3] * il1);
    }
}

// ============================================================================

extern "C" void kernel_launch(void* const* d_in, const int* in_sizes, int n_in,
                              void* d_out, int out_size) {
    (void)out_size;
    // Bind inputs by SIZE (pairwise distinct): x 6,291,456 | W 1,769,472 | b 2,304
    const float* x = nullptr;
    const float* W = nullptr;
    const float* bias = nullptr;
    for (int i = 0; i < n_in; i++) {
        if (in_sizes[i] == M_TOT * EMBED)      x    = (const float*)d_in[i];
        else if (in_sizes[i] == N_TOT * EMBED) W    = (const float*)d_in[i];
        else if (in_sizes[i] == N_TOT)         bias = (const float*)d_in[i];
    }
    float* out = (float*)d_out;

    const int attn_smem = 2 * 128 * HDIM * (int)sizeof(float);  // 65536
    cudaFuncSetAttribute(attn_split, cudaFuncAttributeMaxDynamicSharedMemorySize, attn_smem);

    probe_kernel<<<1, 32>>>();
    qkv_scalar<<<dim3(N_TOT / 128, M_TOT / 128), 256>>>(x, W, bias);
    attn_split<<<BATCH * HEADS * (SEQ / 128), 128, attn_smem>>>(out);
}